// round 17
// baseline (speedup 1.0000x reference)
#include <cuda_runtime.h>
#include <math.h>

#define BATCH   64
#define MAXN    128
#define GH      64
#define GW      32
#define NPTS    2048        // GH*GW
#define NSPLIT  16
#define MAXCHUNK 8          // ceil(MAXN / NSPLIT)
#define NTHREADS 256
#define PPT     8           // NPTS / NTHREADS

typedef unsigned long long u64;

// Partial accumulators: [BATCH][NSPLIT][NPTS] complex (float2) = 16 MB
__device__ float2 g_partial[BATCH * NSPLIT * NPTS];
// Arrival counters (never reset; 16 divides 2^32 so modulo works across replays)
__device__ unsigned int g_arrive[BATCH];

// ---- packed f32x2 helpers ----
__device__ __forceinline__ u64 pk(float lo, float hi) {
    u64 r; asm("mov.b64 %0, {%1,%2};" : "=l"(r) : "f"(lo), "f"(hi)); return r;
}
__device__ __forceinline__ void upk(u64 v, float& lo, float& hi) {
    asm("mov.b64 {%0,%1}, %2;" : "=f"(lo), "=f"(hi) : "l"(v));
}
__device__ __forceinline__ u64 mul2(u64 a, u64 b) {
    u64 d; asm("mul.rn.f32x2 %0, %1, %2;" : "=l"(d) : "l"(a), "l"(b)); return d;
}
__device__ __forceinline__ u64 fma2(u64 a, u64 b, u64 c) {
    u64 d; asm("fma.rn.f32x2 %0, %1, %2, %3;" : "=l"(d) : "l"(a), "l"(b), "l"(c)); return d;
}
__device__ __forceinline__ u64 add2(u64 a, u64 b) {
    u64 d; asm("add.rn.f32x2 %0, %1, %2;" : "=l"(d) : "l"(a), "l"(b)); return d;
}

// pos_w[k] = 0.1 * 10^(k/30), float path: one MUFU EX2, <=3 ulp.
__device__ __forceinline__ float pos_w_fast(int k) {
    return 0.1f * exp2f((float)k * 0.110730936496245417f);
}

#define TWO_PI_F   6.28318530717958648f
#define FOUR_PI2_F (4.0f * 3.14159274101257324f * 3.14159274101257324f)

struct Tri { float xq, yq, xr, yr, xs, ys, area, scale2; };

__global__ __launch_bounds__(NTHREADS)
void pfc_fused_kernel(const float* __restrict__ tris,
                      const int* __restrict__ lengths,
                      float* __restrict__ out) {
    __shared__ float sWx[GH];
    __shared__ float sWy[GW];
    __shared__ Tri   sTri[MAXCHUNK];
    __shared__ float4 sRowQ[2][GH], sRowR[2][GH];
    __shared__ float2 sRowP[2][GH];
    __shared__ float4 sColQ[2][GW], sColR[2][GW];
    __shared__ float2 sColP[2][GW];
    __shared__ int sWin;

    const int tid = threadIdx.x;
    const int b   = blockIdx.x >> 4;        // / NSPLIT
    const int s   = blockIdx.x & (NSPLIT - 1);

    // Build frequency grid in-block, float-only. Exact zeros written literally.
    if (tid < GH) {
        int h = tid;
        float v;
        if (h < 31)       v = -pos_w_fast(30 - h);
        else if (h == 31) v = 0.0f;
        else if (h <= 62) v = pos_w_fast(h - 32);
        else              v = 0.0f;           // padded row
        sWx[h] = v;
    } else if (tid < GH + GW) {
        int w = tid - GH;
        sWy[w] = (w == 0) ? 0.0f : pos_w_fast(w - 1);
    }

    const int len  = lengths[b];
    // interleaved assignment: this split owns triangles s, s+16, s+32, ...
    const int ntri = (len > s) ? ((len - 1 - s) / NSPLIT + 1) : 0;

    if (tid < MAXCHUNK && tid < ntri) {
        const int t = s + tid * NSPLIT;
        const float* p = tris + (size_t)(b * MAXN + t) * 6;
        Tri tr;
        tr.xq = p[0]; tr.yq = p[1];
        tr.xr = p[2]; tr.yr = p[3];
        tr.xs = p[4]; tr.ys = p[5];
        float det = tr.xq * (tr.yr - tr.ys) + tr.xr * (tr.ys - tr.yq)
                  + tr.xs * (tr.yq - tr.yr);
        tr.area   = fabsf(0.5f * det);
        tr.scale2 = 2.0f * tr.area / FOUR_PI2_F;
        sTri[tid] = tr;
    }
    __syncthreads();

    const int w     = tid & 31;
    const int hbase = (tid >> 5) * PPT;

    u64 acc[PPT];
#pragma unroll
    for (int k = 0; k < PPT; k++) acc[k] = 0ull;

    for (int j = 0; j < ntri; j++) {
        const Tri tr = sTri[j];   // broadcast
        const int buf = j & 1;

        // ---- build factored vertex-phasor tables (288 sincos, coop) ----
        if (tid < 192) {
            int h = tid & 63;
            int which = tid >> 6;               // 0:Q 1:R 2:P(=S row)
            float wx = sWx[h];
            float arg, lin;
            if (which == 0)      { arg = wx * tr.xq; lin = wx * (tr.xr - tr.xq); }
            else if (which == 1) { arg = wx * tr.xr; lin = wx * (tr.xs - tr.xr); }
            else                 { arg = wx * tr.xs; lin = 0.0f; }
            float sn, cs;
            sincosf(-TWO_PI_F * arg, &sn, &cs);
            if (which == 0)      sRowQ[buf][h] = make_float4(cs, sn, -sn, lin);
            else if (which == 1) sRowR[buf][h] = make_float4(cs, sn, -sn, lin);
            else                 sRowP[buf][h] = make_float2(cs, sn);
        } else {
            int ww = tid & 31;
            float wy = sWy[ww];
            float arg, lin;
            if (tid < 224) { arg = wy * tr.yq; lin = wy * (tr.yr - tr.yq); }
            else           { arg = wy * tr.yr; lin = wy * (tr.ys - tr.yr); }
            float sn, cs;
            sincosf(-TWO_PI_F * arg, &sn, &cs);
            if (tid < 224) sColQ[buf][ww] = make_float4(cs, sn, lin, 0.0f);
            else           sColR[buf][ww] = make_float4(cs, sn, lin, 0.0f);
        }
        if (tid < 32) {                         // second job: colS phasor
            float wy = sWy[tid];
            float sn, cs;
            sincosf(-TWO_PI_F * (wy * tr.ys), &sn, &cs);
            sColP[buf][tid] = make_float2(cs, sn);
        }
        __syncthreads();   // single barrier per triangle (double buffered)

        // ---- per-triangle column prep (done once, reused over 8 h's) ----
        const float4 cQ = sColQ[buf][w];
        const float4 cR = sColR[buf][w];
        const float2 cS = sColP[buf][w];
        const u64 cQcdN = pk(-cQ.x, -cQ.y);     // negated -> produces -Eq
        const u64 cQdcN = pk(-cQ.y, -cQ.x);
        const u64 cRcd  = pk( cR.x,  cR.y);     // positive -> Er
        const u64 cRdc  = pk( cR.y,  cR.x);
        const u64 cScdN = pk(-cS.x, -cS.y);     // negated -> -Es
        const u64 cSdcN = pk(-cS.y, -cS.x);
        const float cLinU = cQ.z;
        const float cLinV = cR.z;
        const float area   = tr.area;
        const float scale2 = tr.scale2;

#pragma unroll
        for (int k = 0; k < PPT; k++) {
            const int h = hbase + k;            // uniform across the warp
            const float4 rQ = sRowQ[buf][h];
            const float4 rR = sRowR[buf][h];
            const float2 rP = sRowP[buf][h];

            const float U_ = rQ.w + cLinU;
            const float V_ = rR.w + cLinV;
            const float S  = U_ + V_;

            // vertex phasors (row x col complex product), Q and S negated
            u64 EqN = mul2(pk(rQ.x, rQ.x), cQcdN);
            EqN     = fma2(pk(rQ.z, rQ.y), cQdcN, EqN);
            u64 Er  = mul2(pk(rR.x, rR.x), cRcd);
            Er      = fma2(pk(rR.z, rR.y), cRdc, Er);
            u64 EsN = mul2(pk(rP.x, rP.x), cScdN);
            EsN     = fma2(pk(-rP.y, rP.y), cSdcN, EsN);

            if (U_ != 0.0f && V_ != 0.0f && S != 0.0f) {          // normal
                u64 p2 = mul2(pk(U_, U_), EsN);
                p2 = fma2(pk(S, S), Er, p2);
                p2 = fma2(pk(V_, V_), EqN, p2);
                const float scale = __fdividef(scale2, U_ * V_ * S);
                acc[k] = fma2(pk(scale, scale), p2, acc[k]);
            } else {
                float eqr, eqi, esr, esi, erre, erim;
                upk(EqN, eqr, eqi); eqr = -eqr; eqi = -eqi;
                upk(EsN, esr, esi); esr = -esr; esi = -esi;
                upk(Er, erre, erim);
                if (U_ == 0.0f && V_ == 0.0f) {                   // zero
                    acc[k] = add2(acc[k], pk(area, 0.0f));
                } else if (S == 0.0f) {                           // diag
                    const float scale = -__fdividef(scale2, U_ * U_);
                    const float wim = TWO_PI_F * U_;
                    const float tre = erre - eqr - wim * eqi;
                    const float tim = erim - eqi + wim * eqr;
                    acc[k] = fma2(pk(scale, scale), pk(tre, tim), acc[k]);
                } else if (U_ == 0.0f) {                          // u-mask
                    const float scale = -__fdividef(scale2, V_ * V_);
                    const float wim = TWO_PI_F * V_;
                    const float tre = esr - eqr - wim * eqi;
                    const float tim = esi - eqi + wim * eqr;
                    acc[k] = fma2(pk(scale, scale), pk(tre, tim), acc[k]);
                } else {                                          // v-mask
                    const float scale = __fdividef(scale2, U_ * U_);
                    const float wim = TWO_PI_F * U_;
                    const float tre = erre - wim * erim - eqr;
                    const float tim = erim + wim * erre - eqi;
                    acc[k] = fma2(pk(scale, scale), pk(tre, tim), acc[k]);
                }
            }
        }
    }

    // ---- write partials (deterministic STG.64) ----
#pragma unroll
    for (int k = 0; k < PPT; k++) {
        const int p = (hbase + k) * GW + w;
        *reinterpret_cast<u64*>(&g_partial[(b * NSPLIT + s) * NPTS + p]) = acc[k];
    }
    __syncthreads();            // all partial stores of this block issued

    // ---- last-block-per-batch finalizes (fixed s-order => deterministic) ----
    if (tid == 0) {
        __threadfence();        // make partials visible device-wide
        unsigned int old = atomicAdd(&g_arrive[b], 1u);
        sWin = ((old & (NSPLIT - 1)) == (NSPLIT - 1)) ? 1 : 0;
    }
    __syncthreads();
    if (!sWin) return;
    __threadfence();            // acquire: observe all 16 blocks' partials

#pragma unroll
    for (int k = 0; k < PPT; k++) {
        const int p = tid + k * NTHREADS;      // 0 .. 2047
        float re = 0.0f, im = 0.0f;
#pragma unroll
        for (int s2 = 0; s2 < NSPLIT; s2++) {
            const float2 v = g_partial[(b * NSPLIT + s2) * NPTS + p];
            re += v.x; im += v.y;
        }
        const int h = p >> 5;
        const float m2 = re * re + im * im;
        const bool nul = (h == GH - 1) || (m2 == 0.0f);
        const int idx = b * NPTS + p;
        out[idx]                = nul ? 0.0f : log1pf(sqrtf(m2));   // mag
        out[BATCH * NPTS + idx] = nul ? 0.0f : atan2f(im, re);      // phase
    }
}

extern "C" void kernel_launch(void* const* d_in, const int* in_sizes, int n_in,
                              void* d_out, int out_size) {
    const float* tris    = (const float*)d_in[0];   // [64,128,3,2] f32
    const int*   lengths = (const int*)d_in[1];     // [64] i32
    float* out = (float*)d_out;                     // 262144 f32: mag then phase

    pfc_fused_kernel<<<BATCH * NSPLIT, NTHREADS>>>(tris, lengths, out);
}